// round 2
// baseline (speedup 1.0000x reference)
#include <cuda_runtime.h>
#include <math.h>

#define NHEAD  8
#define DMODEL 1024
#define DT     256
#define BATCH  32
#define KSZ    13
#define PADC   6
#define LLEN   1024

// ---------------------------------------------------------------------------
// Scratch arena (static device memory; no allocations anywhere).
// Offsets in floats.
// ---------------------------------------------------------------------------
#define OFF_QB   0ull                       // 32*256*1024        =  8388608
#define OFF_KB   8388608ull
#define OFF_VB   16777216ull
#define OFF_QS   25165824ull                // 8*32*256*256       = 16777216
#define OFF_KS   41943040ull
#define OFF_VS   58720256ull
#define OFF_SC   75497472ull                // scores             = 16777216
#define OFF_CAT  92274688ull                // 32*256*2048        = 16777216
#define OFF_PR   109051904ull               // 32*256*1024        =  8388608
#define OFF_FC   117440512ull
#define WS_TOTAL 125829120ull               // 480 MB

__device__ float g_ws[WS_TOTAL];

// ---------------------------------------------------------------------------
// conv1d: y[b,o,l] = sum_{c,t} w[o,c,t] * x[b,c,l+t-6] + bias[o]
// x: (B, 256, 1024), w: (256, 256, 13). Tile: 64 (o) x 128 (l), chunk 8 chans.
// 256 threads; micro-tile 4(o) x 8(l).
// ---------------------------------------------------------------------------
__global__ __launch_bounds__(256) void conv1d_kernel(
    const float* __restrict__ x, const float* __restrict__ w,
    const float* __restrict__ bias, float* __restrict__ y)
{
    const int b  = blockIdx.z;
    const int o0 = blockIdx.y * 64;
    const int l0 = blockIdx.x * 128;

    __shared__ float Ws[64][8 * KSZ];            // 64 x 104
    __shared__ float Xs[8][128 + 2 * PADC];      // 8 x 140

    const int tid = threadIdx.x;
    const int tl  = tid & 15;    // l group
    const int to  = tid >> 4;    // o group (0..15)

    float acc[4][8];
#pragma unroll
    for (int i = 0; i < 4; i++)
#pragma unroll
        for (int j = 0; j < 8; j++) acc[i][j] = 0.f;

    const float* xb = x + (size_t)b * 256 * LLEN;

    for (int c0 = 0; c0 < 256; c0 += 8) {
        // load weights: Ws[o][c*13+t] = w[(o0+o)*256*13 + (c0)*13 + r]
        for (int i = tid; i < 64 * 8 * KSZ; i += 256) {
            int o = i / (8 * KSZ);
            int r = i - o * (8 * KSZ);
            Ws[o][r] = w[(size_t)(o0 + o) * 256 * KSZ + (size_t)c0 * KSZ + r];
        }
        // load inputs with halo + zero padding
        for (int i = tid; i < 8 * 140; i += 256) {
            int c = i / 140;
            int j = i - c * 140;
            int l = l0 + j - PADC;
            Xs[c][j] = (l >= 0 && l < LLEN) ? xb[(size_t)(c0 + c) * LLEN + l] : 0.f;
        }
        __syncthreads();

#pragma unroll
        for (int c = 0; c < 8; ++c) {
#pragma unroll
            for (int t = 0; t < KSZ; ++t) {
                float wv[4], xv[8];
#pragma unroll
                for (int i = 0; i < 4; i++) wv[i] = Ws[to + 16 * i][c * KSZ + t];
#pragma unroll
                for (int j = 0; j < 8; j++) xv[j] = Xs[c][tl + 16 * j + t];
#pragma unroll
                for (int i = 0; i < 4; i++)
#pragma unroll
                    for (int j = 0; j < 8; j++) acc[i][j] += wv[i] * xv[j];
            }
        }
        __syncthreads();
    }

#pragma unroll
    for (int i = 0; i < 4; i++) {
        const int o = o0 + to + 16 * i;
        const float bi = bias[o];
        float* yr = y + ((size_t)b * 256 + o) * LLEN + l0;
#pragma unroll
        for (int j = 0; j < 8; j++) yr[tl + 16 * j] = acc[i][j] + bi;
    }
}

// ---------------------------------------------------------------------------
// gemm_nn: C = A * B  (A row-major MxK, B row-major KxN), batched over grid.z.
// Tiles 128x128, K-chunk 16, 256 threads, 8x8 micro-tile.
// Batch offsets: z1 = z / Z2, z2 = z % Z2; off = z1*?1 + z2*?2.
// ---------------------------------------------------------------------------
__global__ __launch_bounds__(256) void gemm_nn_k(
    const float* __restrict__ A, const float* __restrict__ B, float* __restrict__ C,
    int K, int lda, int ldb, int ldc, int Z2,
    long a1, long a2, long b1, long b2, long c1, long c2)
{
    const int z  = blockIdx.z;
    const int z1 = z / Z2, z2 = z - z1 * Z2;
    A += (size_t)(z1 * a1 + z2 * a2);
    B += (size_t)(z1 * b1 + z2 * b2);
    C += (size_t)(z1 * c1 + z2 * c2);

    const int m0 = blockIdx.y * 128;
    const int n0 = blockIdx.x * 128;

    __shared__ __align__(16) float As[16][132];   // [k][m] with pad
    __shared__ __align__(16) float Bs[16][128];   // [k][n]

    const int tid = threadIdx.x;
    const int tm  = tid & 15;
    const int tn  = tid >> 4;

    float acc[8][8];
#pragma unroll
    for (int i = 0; i < 8; i++)
#pragma unroll
        for (int j = 0; j < 8; j++) acc[i][j] = 0.f;

    for (int k0 = 0; k0 < K; k0 += 16) {
        // A tile: 128 rows x 16 k, stored transposed [k][m]
#pragma unroll
        for (int i = tid; i < 128 * 16; i += 256) {
            int r = i >> 4, c = i & 15;
            As[c][r] = A[(size_t)(m0 + r) * lda + k0 + c];
        }
        // B tile: 16 rows x 128 n, float4
#pragma unroll
        for (int i = tid; i < 16 * 32; i += 256) {
            int r = i >> 5, c4 = (i & 31) << 2;
            *(float4*)&Bs[r][c4] = *(const float4*)&B[(size_t)(k0 + r) * ldb + n0 + c4];
        }
        __syncthreads();

#pragma unroll
        for (int kk = 0; kk < 16; ++kk) {
            float a[8], bb[8];
#pragma unroll
            for (int i = 0; i < 8; i++) a[i] = As[kk][tm + 16 * i];
#pragma unroll
            for (int j = 0; j < 8; j++) bb[j] = Bs[kk][tn + 16 * j];
#pragma unroll
            for (int i = 0; i < 8; i++)
#pragma unroll
                for (int j = 0; j < 8; j++) acc[i][j] += a[i] * bb[j];
        }
        __syncthreads();
    }

#pragma unroll
    for (int i = 0; i < 8; i++) {
        float* cr = C + (size_t)(m0 + tm + 16 * i) * ldc + n0;
#pragma unroll
        for (int j = 0; j < 8; j++) cr[tn + 16 * j] = acc[i][j];
    }
}

// ---------------------------------------------------------------------------
// gemm_nt: C = alpha * A * B^T + bias   (A: MxK row-major, B: NxK row-major)
// Both operands K-contiguous. Tiles 128x128, K-chunk 16.
// ---------------------------------------------------------------------------
__global__ __launch_bounds__(256) void gemm_nt_k(
    const float* __restrict__ A, const float* __restrict__ B, float* __restrict__ C,
    int K, int lda, int ldb, int ldc, int Z2,
    long a1, long a2, long b1, long b2, long c1, long c2,
    float alpha, const float* __restrict__ bias)
{
    const int z  = blockIdx.z;
    const int z1 = z / Z2, z2 = z - z1 * Z2;
    A += (size_t)(z1 * a1 + z2 * a2);
    B += (size_t)(z1 * b1 + z2 * b2);
    C += (size_t)(z1 * c1 + z2 * c2);

    const int m0 = blockIdx.y * 128;
    const int n0 = blockIdx.x * 128;

    __shared__ __align__(16) float As[128][17];
    __shared__ __align__(16) float Bs[128][17];

    const int tid = threadIdx.x;
    const int tm  = tid & 15;
    const int tn  = tid >> 4;

    float acc[8][8];
#pragma unroll
    for (int i = 0; i < 8; i++)
#pragma unroll
        for (int j = 0; j < 8; j++) acc[i][j] = 0.f;

    for (int k0 = 0; k0 < K; k0 += 16) {
#pragma unroll
        for (int i = tid; i < 128 * 16; i += 256) {
            int r = i >> 4, c = i & 15;
            As[r][c] = A[(size_t)(m0 + r) * lda + k0 + c];
        }
#pragma unroll
        for (int i = tid; i < 128 * 16; i += 256) {
            int r = i >> 4, c = i & 15;
            Bs[r][c] = B[(size_t)(n0 + r) * ldb + k0 + c];
        }
        __syncthreads();

#pragma unroll
        for (int kk = 0; kk < 16; ++kk) {
            float a[8], bb[8];
#pragma unroll
            for (int i = 0; i < 8; i++) a[i] = As[tm + 16 * i][kk];
#pragma unroll
            for (int j = 0; j < 8; j++) bb[j] = Bs[tn + 16 * j][kk];
#pragma unroll
            for (int i = 0; i < 8; i++)
#pragma unroll
                for (int j = 0; j < 8; j++) acc[i][j] += a[i] * bb[j];
        }
        __syncthreads();
    }

#pragma unroll
    for (int i = 0; i < 8; i++) {
        float* cr = C + (size_t)(m0 + tm + 16 * i) * ldc + n0;
#pragma unroll
        for (int j = 0; j < 8; j++) {
            float bv = bias ? bias[n0 + tn + 16 * j] : 0.f;
            cr[tn + 16 * j] = alpha * acc[i][j] + bv;
        }
    }
}

// ---------------------------------------------------------------------------
// softmax over last axis (256). One warp per row; 8 rows per block.
// ---------------------------------------------------------------------------
__global__ __launch_bounds__(256) void softmax_kernel(
    const float* __restrict__ scores, float* __restrict__ attn)
{
    const int row  = blockIdx.x * 8 + (threadIdx.x >> 5);
    const int lane = threadIdx.x & 31;
    const float* s = scores + (size_t)row * 256;

    float v[8];
    float mx = -1e30f;
#pragma unroll
    for (int j = 0; j < 8; j++) { v[j] = s[lane + 32 * j]; mx = fmaxf(mx, v[j]); }
#pragma unroll
    for (int o = 16; o; o >>= 1) mx = fmaxf(mx, __shfl_xor_sync(0xffffffffu, mx, o));

    float sum = 0.f;
#pragma unroll
    for (int j = 0; j < 8; j++) { v[j] = expf(v[j] - mx); sum += v[j]; }
#pragma unroll
    for (int o = 16; o; o >>= 1) sum += __shfl_xor_sync(0xffffffffu, sum, o);

    const float inv = 1.f / sum;
    float* a = attn + (size_t)row * 256;
#pragma unroll
    for (int j = 0; j < 8; j++) a[lane + 32 * j] = v[j] * inv;
}

// ---------------------------------------------------------------------------
// residual + LayerNorm (ddof=1, eps added to sigma). Row = 1024, one block/row.
// ---------------------------------------------------------------------------
__global__ __launch_bounds__(256) void ln_kernel(
    const float* __restrict__ fc, const float* __restrict__ q,
    const float* __restrict__ ga, const float* __restrict__ gb,
    float* __restrict__ out)
{
    const int row = blockIdx.x;
    const float* f  = fc + (size_t)row * DMODEL;
    const float* qq = q  + (size_t)row * DMODEL;
    const int tid = threadIdx.x;

    float zv[4];
    float s = 0.f, ss = 0.f;
#pragma unroll
    for (int j = 0; j < 4; j++) {
        float zz = f[tid + 256 * j] + qq[tid + 256 * j];
        zv[j] = zz; s += zz; ss += zz * zz;
    }

    __shared__ float rs[8], rss[8];
#pragma unroll
    for (int o = 16; o; o >>= 1) {
        s  += __shfl_xor_sync(0xffffffffu, s, o);
        ss += __shfl_xor_sync(0xffffffffu, ss, o);
    }
    if ((tid & 31) == 0) { rs[tid >> 5] = s; rss[tid >> 5] = ss; }
    __syncthreads();
    if (tid < 32) {
        float a = (tid < 8) ? rs[tid] : 0.f;
        float b = (tid < 8) ? rss[tid] : 0.f;
#pragma unroll
        for (int o = 4; o; o >>= 1) {
            a += __shfl_xor_sync(0xffffffffu, a, o);
            b += __shfl_xor_sync(0xffffffffu, b, o);
        }
        if (tid == 0) { rs[0] = a; rss[0] = b; }
    }
    __syncthreads();

    const float mu  = rs[0] * (1.f / DMODEL);
    const float var = (rss[0] - (float)DMODEL * mu * mu) * (1.f / (DMODEL - 1));
    const float inv = 1.f / (sqrtf(fmaxf(var, 0.f)) + 1e-3f);

    float* o_ = out + (size_t)row * DMODEL;
#pragma unroll
    for (int j = 0; j < 4; j++) {
        const int col = tid + 256 * j;
        o_[col] = (zv[j] - mu) * inv * ga[col] + gb[col];
    }
}

// ---------------------------------------------------------------------------
extern "C" void kernel_launch(void* const* d_in, const int* in_sizes, int n_in,
                              void* d_out, int out_size)
{
    const float* q    = (const float*)d_in[0];
    const float* k    = (const float*)d_in[1];
    const float* v    = (const float*)d_in[2];
    const float* cq_w = (const float*)d_in[3];
    const float* cq_b = (const float*)d_in[4];
    const float* ck_w = (const float*)d_in[5];
    const float* ck_b = (const float*)d_in[6];
    const float* cv_w = (const float*)d_in[7];
    const float* cv_b = (const float*)d_in[8];
    const float* w_qs = (const float*)d_in[9];
    const float* w_ks = (const float*)d_in[10];
    const float* w_vs = (const float*)d_in[11];
    const float* pj_w = (const float*)d_in[12];
    const float* pj_b = (const float*)d_in[13];
    const float* fc_w = (const float*)d_in[14];
    const float* fc_b = (const float*)d_in[15];
    const float* ln_a = (const float*)d_in[16];
    const float* ln_b = (const float*)d_in[17];

    float* ws = nullptr;
    cudaGetSymbolAddress((void**)&ws, g_ws);
    float* qb  = ws + OFF_QB;
    float* kb  = ws + OFF_KB;
    float* vb  = ws + OFF_VB;
    float* qs  = ws + OFF_QS;
    float* ks_ = ws + OFF_KS;
    float* vs  = ws + OFF_VS;
    float* sc  = ws + OFF_SC;
    float* cat = ws + OFF_CAT;
    float* pr  = ws + OFF_PR;
    float* fc  = ws + OFF_FC;

    float* out  = (float*)d_out;
    float* attn = out + (size_t)BATCH * DT * LLEN;   // attns region of d_out

    const dim3 cgrid(LLEN / 128, DT / 64, BATCH);

    // 1. conv1d "projections"
    conv1d_kernel<<<cgrid, 256>>>(q, cq_w, cq_b, qb);
    conv1d_kernel<<<cgrid, 256>>>(k, ck_w, ck_b, kb);
    conv1d_kernel<<<cgrid, 256>>>(v, cv_w, cv_b, vb);

    // 2. per-head projections: qs[h,b] = qb[b] (256x1024) * w_qs[h] (1024x256)
    // z = h*32 + b
    const dim3 ghb(2, 2, NHEAD * BATCH);
    gemm_nn_k<<<ghb, 256>>>(qb, w_qs, qs, 1024, 1024, 256, 256, 32,
                            0, (long)DT * LLEN, (long)LLEN * DT, 0,
                            32L * 65536, 65536);
    gemm_nn_k<<<ghb, 256>>>(kb, w_ks, ks_, 1024, 1024, 256, 256, 32,
                            0, (long)DT * LLEN, (long)LLEN * DT, 0,
                            32L * 65536, 65536);
    gemm_nn_k<<<ghb, 256>>>(vb, w_vs, vs, 1024, 1024, 256, 256, 32,
                            0, (long)DT * LLEN, (long)LLEN * DT, 0,
                            32L * 65536, 65536);

    // 3. scores = qs * ks^T / sqrt(1024)
    gemm_nt_k<<<ghb, 256>>>(qs, ks_, sc, 256, 256, 256, 256, 1,
                            65536, 0, 65536, 0, 65536, 0,
                            1.f / 32.f, nullptr);

    // 4. softmax -> attns output region (layout (H*B, 256, 256) matches)
    softmax_kernel<<<(NHEAD * BATCH * DT) / 8, 256>>>(sc, attn);

    // 5. out = attn * vs, written directly into concat layout (B, 256, H*256)
    gemm_nn_k<<<ghb, 256>>>(attn, vs, cat, 256, 256, 256, NHEAD * DT, 32,
                            32L * 65536, 65536, 32L * 65536, 65536,
                            256, (long)DT * NHEAD * DT);

    // 6. proj: (B,256,2048) @ proj_w^T (+ bias) -> (B,256,1024)   [NT GEMM]
    const dim3 gproj(DMODEL / 128, DT / 128, BATCH);
    gemm_nt_k<<<gproj, 256>>>(cat, pj_w, pr, NHEAD * DT,
                              NHEAD * DT, NHEAD * DT, DMODEL, 1,
                              (long)DT * NHEAD * DT, 0, 0, 0,
                              (long)DT * DMODEL, 0,
                              1.f, pj_b);

    // 7. fc conv1d
    conv1d_kernel<<<cgrid, 256>>>(pr, fc_w, fc_b, fc);

    // 8. residual + LayerNorm -> output region of d_out
    ln_kernel<<<BATCH * DT, 256>>>(fc, q, ln_a, ln_b, out);

    (void)in_sizes; (void)n_in; (void)out_size;
}

// round 4
// speedup vs baseline: 1.0032x; 1.0032x over previous
#include <cuda_runtime.h>
#include <math.h>

#define NHEAD  8
#define DMODEL 1024
#define DT     256
#define BATCH  32
#define KSZ    13
#define PADC   6
#define LLEN   1024

// ---------------------------------------------------------------------------
// Scratch arena (static device memory; no allocations anywhere).
// Offsets in floats.
// ---------------------------------------------------------------------------
#define OFF_QB   0ull                       // 32*256*1024        =  8388608
#define OFF_KB   8388608ull
#define OFF_VB   16777216ull
#define OFF_QS   25165824ull                // 8*32*256*256       = 16777216
#define OFF_KS   41943040ull
#define OFF_VS   58720256ull
#define OFF_SC   75497472ull                // scores             = 16777216
#define OFF_CAT  92274688ull                // 32*256*2048        = 16777216
#define OFF_PR   109051904ull               // 32*256*1024        =  8388608
#define OFF_FC   117440512ull
#define WS_TOTAL 125829120ull               // 480 MB

__device__ float g_ws[WS_TOTAL];

// ---------------------------------------------------------------------------
// conv1d: y[b,o,l] = sum_{c,t} w[o,c,t] * x[b,c,l+t-6] + bias[o]
// x: (B, 256, 1024), w: (256, 256, 13). Tile: 64 (o) x 128 (l), chunk 8 chans.
// 256 threads; micro-tile 4(o) x 8(l).
// ---------------------------------------------------------------------------
__global__ __launch_bounds__(256) void conv1d_kernel(
    const float* __restrict__ x, const float* __restrict__ w,
    const float* __restrict__ bias, float* __restrict__ y)
{
    const int b  = blockIdx.z;
    const int o0 = blockIdx.y * 64;
    const int l0 = blockIdx.x * 128;

    __shared__ float Ws[64][8 * KSZ];            // 64 x 104
    __shared__ float Xs[8][128 + 2 * PADC];      // 8 x 140

    const int tid = threadIdx.x;
    const int tl  = tid & 15;    // l group
    const int to  = tid >> 4;    // o group (0..15)

    float acc[4][8];
#pragma unroll
    for (int i = 0; i < 4; i++)
#pragma unroll
        for (int j = 0; j < 8; j++) acc[i][j] = 0.f;

    const float* xb = x + (size_t)b * 256 * LLEN;

    for (int c0 = 0; c0 < 256; c0 += 8) {
        // load weights: Ws[o][c*13+t] = w[(o0+o)*256*13 + (c0)*13 + r]
        for (int i = tid; i < 64 * 8 * KSZ; i += 256) {
            int o = i / (8 * KSZ);
            int r = i - o * (8 * KSZ);
            Ws[o][r] = w[(size_t)(o0 + o) * 256 * KSZ + (size_t)c0 * KSZ + r];
        }
        // load inputs with halo + zero padding
        for (int i = tid; i < 8 * 140; i += 256) {
            int c = i / 140;
            int j = i - c * 140;
            int l = l0 + j - PADC;
            Xs[c][j] = (l >= 0 && l < LLEN) ? xb[(size_t)(c0 + c) * LLEN + l] : 0.f;
        }
        __syncthreads();

#pragma unroll
        for (int c = 0; c < 8; ++c) {
#pragma unroll
            for (int t = 0; t < KSZ; ++t) {
                float wv[4], xv[8];
#pragma unroll
                for (int i = 0; i < 4; i++) wv[i] = Ws[to + 16 * i][c * KSZ + t];
#pragma unroll
                for (int j = 0; j < 8; j++) xv[j] = Xs[c][tl + 16 * j + t];
#pragma unroll
                for (int i = 0; i < 4; i++)
#pragma unroll
                    for (int j = 0; j < 8; j++) acc[i][j] += wv[i] * xv[j];
            }
        }
        __syncthreads();
    }

#pragma unroll
    for (int i = 0; i < 4; i++) {
        const int o = o0 + to + 16 * i;
        const float bi = bias[o];
        float* yr = y + ((size_t)b * 256 + o) * LLEN + l0;
#pragma unroll
        for (int j = 0; j < 8; j++) yr[tl + 16 * j] = acc[i][j] + bi;
    }
}

// ---------------------------------------------------------------------------
// gemm_nn: C = A * B  (A row-major MxK, B row-major KxN), batched over grid.z.
// Tiles 128x128, K-chunk 16, 256 threads, 8x8 micro-tile.
// Batch offsets: z1 = z / Z2, z2 = z % Z2; off = z1*?1 + z2*?2.
// ---------------------------------------------------------------------------
__global__ __launch_bounds__(256) void gemm_nn_k(
    const float* __restrict__ A, const float* __restrict__ B, float* __restrict__ C,
    int K, int lda, int ldb, int ldc, int Z2,
    long a1, long a2, long b1, long b2, long c1, long c2)
{
    const int z  = blockIdx.z;
    const int z1 = z / Z2, z2 = z - z1 * Z2;
    A += (size_t)(z1 * a1 + z2 * a2);
    B += (size_t)(z1 * b1 + z2 * b2);
    C += (size_t)(z1 * c1 + z2 * c2);

    const int m0 = blockIdx.y * 128;
    const int n0 = blockIdx.x * 128;

    __shared__ __align__(16) float As[16][132];   // [k][m] with pad
    __shared__ __align__(16) float Bs[16][128];   // [k][n]

    const int tid = threadIdx.x;
    const int tm  = tid & 15;
    const int tn  = tid >> 4;

    float acc[8][8];
#pragma unroll
    for (int i = 0; i < 8; i++)
#pragma unroll
        for (int j = 0; j < 8; j++) acc[i][j] = 0.f;

    for (int k0 = 0; k0 < K; k0 += 16) {
        // A tile: 128 rows x 16 k, stored transposed [k][m]
#pragma unroll
        for (int i = tid; i < 128 * 16; i += 256) {
            int r = i >> 4, c = i & 15;
            As[c][r] = A[(size_t)(m0 + r) * lda + k0 + c];
        }
        // B tile: 16 rows x 128 n, float4
#pragma unroll
        for (int i = tid; i < 16 * 32; i += 256) {
            int r = i >> 5, c4 = (i & 31) << 2;
            *(float4*)&Bs[r][c4] = *(const float4*)&B[(size_t)(k0 + r) * ldb + n0 + c4];
        }
        __syncthreads();

#pragma unroll
        for (int kk = 0; kk < 16; ++kk) {
            float a[8], bb[8];
#pragma unroll
            for (int i = 0; i < 8; i++) a[i] = As[kk][tm + 16 * i];
#pragma unroll
            for (int j = 0; j < 8; j++) bb[j] = Bs[kk][tn + 16 * j];
#pragma unroll
            for (int i = 0; i < 8; i++)
#pragma unroll
                for (int j = 0; j < 8; j++) acc[i][j] += a[i] * bb[j];
        }
        __syncthreads();
    }

#pragma unroll
    for (int i = 0; i < 8; i++) {
        float* cr = C + (size_t)(m0 + tm + 16 * i) * ldc + n0;
#pragma unroll
        for (int j = 0; j < 8; j++) cr[tn + 16 * j] = acc[i][j];
    }
}

// ---------------------------------------------------------------------------
// gemm_nt: C = alpha * A * B^T + bias   (A: MxK row-major, B: NxK row-major)
// Both operands K-contiguous. Tiles 128x128, K-chunk 16.
// ---------------------------------------------------------------------------
__global__ __launch_bounds__(256) void gemm_nt_k(
    const float* __restrict__ A, const float* __restrict__ B, float* __restrict__ C,
    int K, int lda, int ldb, int ldc, int Z2,
    long a1, long a2, long b1, long b2, long c1, long c2,
    float alpha, const float* __restrict__ bias)
{
    const int z  = blockIdx.z;
    const int z1 = z / Z2, z2 = z - z1 * Z2;
    A += (size_t)(z1 * a1 + z2 * a2);
    B += (size_t)(z1 * b1 + z2 * b2);
    C += (size_t)(z1 * c1 + z2 * c2);

    const int m0 = blockIdx.y * 128;
    const int n0 = blockIdx.x * 128;

    __shared__ __align__(16) float As[128][17];
    __shared__ __align__(16) float Bs[128][17];

    const int tid = threadIdx.x;
    const int tm  = tid & 15;
    const int tn  = tid >> 4;

    float acc[8][8];
#pragma unroll
    for (int i = 0; i < 8; i++)
#pragma unroll
        for (int j = 0; j < 8; j++) acc[i][j] = 0.f;

    for (int k0 = 0; k0 < K; k0 += 16) {
#pragma unroll
        for (int i = tid; i < 128 * 16; i += 256) {
            int r = i >> 4, c = i & 15;
            As[r][c] = A[(size_t)(m0 + r) * lda + k0 + c];
        }
#pragma unroll
        for (int i = tid; i < 128 * 16; i += 256) {
            int r = i >> 4, c = i & 15;
            Bs[r][c] = B[(size_t)(n0 + r) * ldb + k0 + c];
        }
        __syncthreads();

#pragma unroll
        for (int kk = 0; kk < 16; ++kk) {
            float a[8], bb[8];
#pragma unroll
            for (int i = 0; i < 8; i++) a[i] = As[tm + 16 * i][kk];
#pragma unroll
            for (int j = 0; j < 8; j++) bb[j] = Bs[tn + 16 * j][kk];
#pragma unroll
            for (int i = 0; i < 8; i++)
#pragma unroll
                for (int j = 0; j < 8; j++) acc[i][j] += a[i] * bb[j];
        }
        __syncthreads();
    }

#pragma unroll
    for (int i = 0; i < 8; i++) {
        float* cr = C + (size_t)(m0 + tm + 16 * i) * ldc + n0;
#pragma unroll
        for (int j = 0; j < 8; j++) {
            float bv = bias ? bias[n0 + tn + 16 * j] : 0.f;
            cr[tn + 16 * j] = alpha * acc[i][j] + bv;
        }
    }
}

// ---------------------------------------------------------------------------
// softmax over last axis (256). One warp per row; 8 rows per block.
// ---------------------------------------------------------------------------
__global__ __launch_bounds__(256) void softmax_kernel(
    const float* __restrict__ scores, float* __restrict__ attn)
{
    const int row  = blockIdx.x * 8 + (threadIdx.x >> 5);
    const int lane = threadIdx.x & 31;
    const float* s = scores + (size_t)row * 256;

    float v[8];
    float mx = -1e30f;
#pragma unroll
    for (int j = 0; j < 8; j++) { v[j] = s[lane + 32 * j]; mx = fmaxf(mx, v[j]); }
#pragma unroll
    for (int o = 16; o; o >>= 1) mx = fmaxf(mx, __shfl_xor_sync(0xffffffffu, mx, o));

    float sum = 0.f;
#pragma unroll
    for (int j = 0; j < 8; j++) { v[j] = expf(v[j] - mx); sum += v[j]; }
#pragma unroll
    for (int o = 16; o; o >>= 1) sum += __shfl_xor_sync(0xffffffffu, sum, o);

    const float inv = 1.f / sum;
    float* a = attn + (size_t)row * 256;
#pragma unroll
    for (int j = 0; j < 8; j++) a[lane + 32 * j] = v[j] * inv;
}

// ---------------------------------------------------------------------------
// residual + LayerNorm (ddof=1, eps added to sigma). Row = 1024, one block/row.
// ---------------------------------------------------------------------------
__global__ __launch_bounds__(256) void ln_kernel(
    const float* __restrict__ fc, const float* __restrict__ q,
    const float* __restrict__ ga, const float* __restrict__ gb,
    float* __restrict__ out)
{
    const int row = blockIdx.x;
    const float* f  = fc + (size_t)row * DMODEL;
    const float* qq = q  + (size_t)row * DMODEL;
    const int tid = threadIdx.x;

    float zv[4];
    float s = 0.f, ss = 0.f;
#pragma unroll
    for (int j = 0; j < 4; j++) {
        float zz = f[tid + 256 * j] + qq[tid + 256 * j];
        zv[j] = zz; s += zz; ss += zz * zz;
    }

    __shared__ float rs[8], rss[8];
#pragma unroll
    for (int o = 16; o; o >>= 1) {
        s  += __shfl_xor_sync(0xffffffffu, s, o);
        ss += __shfl_xor_sync(0xffffffffu, ss, o);
    }
    if ((tid & 31) == 0) { rs[tid >> 5] = s; rss[tid >> 5] = ss; }
    __syncthreads();
    if (tid < 32) {
        float a = (tid < 8) ? rs[tid] : 0.f;
        float b = (tid < 8) ? rss[tid] : 0.f;
#pragma unroll
        for (int o = 4; o; o >>= 1) {
            a += __shfl_xor_sync(0xffffffffu, a, o);
            b += __shfl_xor_sync(0xffffffffu, b, o);
        }
        if (tid == 0) { rs[0] = a; rss[0] = b; }
    }
    __syncthreads();

    const float mu  = rs[0] * (1.f / DMODEL);
    const float var = (rss[0] - (float)DMODEL * mu * mu) * (1.f / (DMODEL - 1));
    const float inv = 1.f / (sqrtf(fmaxf(var, 0.f)) + 1e-3f);

    float* o_ = out + (size_t)row * DMODEL;
#pragma unroll
    for (int j = 0; j < 4; j++) {
        const int col = tid + 256 * j;
        o_[col] = (zv[j] - mu) * inv * ga[col] + gb[col];
    }
}

// ---------------------------------------------------------------------------
extern "C" void kernel_launch(void* const* d_in, const int* in_sizes, int n_in,
                              void* d_out, int out_size)
{
    const float* q    = (const float*)d_in[0];
    const float* k    = (const float*)d_in[1];
    const float* v    = (const float*)d_in[2];
    const float* cq_w = (const float*)d_in[3];
    const float* cq_b = (const float*)d_in[4];
    const float* ck_w = (const float*)d_in[5];
    const float* ck_b = (const float*)d_in[6];
    const float* cv_w = (const float*)d_in[7];
    const float* cv_b = (const float*)d_in[8];
    const float* w_qs = (const float*)d_in[9];
    const float* w_ks = (const float*)d_in[10];
    const float* w_vs = (const float*)d_in[11];
    const float* pj_w = (const float*)d_in[12];
    const float* pj_b = (const float*)d_in[13];
    const float* fc_w = (const float*)d_in[14];
    const float* fc_b = (const float*)d_in[15];
    const float* ln_a = (const float*)d_in[16];
    const float* ln_b = (const float*)d_in[17];

    float* ws = nullptr;
    cudaGetSymbolAddress((void**)&ws, g_ws);
    float* qb  = ws + OFF_QB;
    float* kb  = ws + OFF_KB;
    float* vb  = ws + OFF_VB;
    float* qs  = ws + OFF_QS;
    float* ks_ = ws + OFF_KS;
    float* vs  = ws + OFF_VS;
    float* sc  = ws + OFF_SC;
    float* cat = ws + OFF_CAT;
    float* pr  = ws + OFF_PR;
    float* fc  = ws + OFF_FC;

    float* out  = (float*)d_out;
    float* attn = out + (size_t)BATCH * DT * LLEN;   // attns region of d_out

    const dim3 cgrid(LLEN / 128, DT / 64, BATCH);

    // 1. conv1d "projections"
    conv1d_kernel<<<cgrid, 256>>>(q, cq_w, cq_b, qb);
    conv1d_kernel<<<cgrid, 256>>>(k, ck_w, ck_b, kb);
    conv1d_kernel<<<cgrid, 256>>>(v, cv_w, cv_b, vb);

    // 2. per-head projections: qs[h,b] = qb[b] (256x1024) * w_qs[h] (1024x256)
    // z = h*32 + b
    const dim3 ghb(2, 2, NHEAD * BATCH);
    gemm_nn_k<<<ghb, 256>>>(qb, w_qs, qs, 1024, 1024, 256, 256, 32,
                            0, (long)DT * LLEN, (long)LLEN * DT, 0,
                            32L * 65536, 65536);
    gemm_nn_k<<<ghb, 256>>>(kb, w_ks, ks_, 1024, 1024, 256, 256, 32,
                            0, (long)DT * LLEN, (long)LLEN * DT, 0,
                            32L * 65536, 65536);
    gemm_nn_k<<<ghb, 256>>>(vb, w_vs, vs, 1024, 1024, 256, 256, 32,
                            0, (long)DT * LLEN, (long)LLEN * DT, 0,
                            32L * 65536, 65536);

    // 3. scores = qs * ks^T / sqrt(1024)
    gemm_nt_k<<<ghb, 256>>>(qs, ks_, sc, 256, 256, 256, 256, 1,
                            65536, 0, 65536, 0, 65536, 0,
                            1.f / 32.f, nullptr);

    // 4. softmax -> attns output region (layout (H*B, 256, 256) matches)
    softmax_kernel<<<(NHEAD * BATCH * DT) / 8, 256>>>(sc, attn);

    // 5. out = attn * vs, written directly into concat layout (B, 256, H*256)
    gemm_nn_k<<<ghb, 256>>>(attn, vs, cat, 256, 256, 256, NHEAD * DT, 32,
                            32L * 65536, 65536, 32L * 65536, 65536,
                            256, (long)DT * NHEAD * DT);

    // 6. proj: (B,256,2048) @ proj_w^T (+ bias) -> (B,256,1024)   [NT GEMM]
    const dim3 gproj(DMODEL / 128, DT / 128, BATCH);
    gemm_nt_k<<<gproj, 256>>>(cat, pj_w, pr, NHEAD * DT,
                              NHEAD * DT, NHEAD * DT, DMODEL, 1,
                              (long)DT * NHEAD * DT, 0, 0, 0,
                              (long)DT * DMODEL, 0,
                              1.f, pj_b);

    // 7. fc conv1d
    conv1d_kernel<<<cgrid, 256>>>(pr, fc_w, fc_b, fc);

    // 8. residual + LayerNorm -> output region of d_out
    ln_kernel<<<BATCH * DT, 256>>>(fc, q, ln_a, ln_b, out);

    (void)in_sizes; (void)n_in; (void)out_size;
}